// round 15
// baseline (speedup 1.0000x reference)
#include <cuda_runtime.h>
#include <cuda_bf16.h>
#include <cuda_fp16.h>
#include <math.h>

#define N_NODES 100000
#define N_EDGES 3200000
#define N_GRAPHS 64
#define F 16
#define NB ((N_NODES + 255) / 256)   // 391 blocks of 256

// ---------------- scratch (static device memory; no allocation) ----------------
// Invariant: d_deg, d_cnt, d_gsum, d_gcnt, d_total are ZERO before every launch
// (zero-initialized at load; each launch re-zeroes them after last use).
__device__ int    d_deg[N_NODES];        // out-degree over row (source)
__device__ int    d_cnt[N_NODES];        // in-count over col (target)
__device__ int    d_off[N_NODES];        // CSR offsets
__device__ int    d_rank[N_EDGES];       // edge rank within its target segment (from hist)
__device__ int    d_total;               // running base for block offsets
__device__ int2   d_csr[N_EDGES];        // {row, half2(ea.x, ea.y)}, grouped by col (8B)
__device__ float  d_dis[N_NODES];        // deg_inv_sqrt
__device__ uint2  d_xh[N_NODES];         // {half2(dis*x0, dis*x1), half2(dis*x2, dis)}
__device__ float2 d_zea[N_NODES];        // per-node Σ nr*ea (layer-independent)
__device__ float  d_h[N_NODES * F];      // layer-1 output (fp32, center path)
__device__ __half d_hh[N_NODES * F];     // dis[n]*h[n] fp16 shadow (gather path)
__device__ float  d_gsum[N_GRAPHS * F];  // pooled sums
__device__ int    d_gcnt[N_GRAPHS];      // nodes per graph

// ---------------- kernels ----------------

// histograms, 4 edges per thread; keeps the cnt-atomic return as the edge's rank
__global__ void k_hist(const int* __restrict__ ei) {
    int t = blockIdx.x * blockDim.x + threadIdx.x;
    int e = t * 4;
    if (e >= N_EDGES) return;            // N_EDGES % 4 == 0, no tail
    int4 r4 = *(const int4*)&ei[e];
    int4 c4 = *(const int4*)&ei[N_EDGES + e];
    atomicAdd(&d_deg[r4.x], 1);
    atomicAdd(&d_deg[r4.y], 1);
    atomicAdd(&d_deg[r4.z], 1);
    atomicAdd(&d_deg[r4.w], 1);
    int4 rk;
    rk.x = atomicAdd(&d_cnt[c4.x], 1);
    rk.y = atomicAdd(&d_cnt[c4.y], 1);
    rk.z = atomicAdd(&d_cnt[c4.z], 1);
    rk.w = atomicAdd(&d_cnt[c4.w], 1);
    *(int4*)&d_rank[e] = rk;             // coalesced
}

// offsets via local scan + atomic block base (order-free), fused finalize.
// Stores premultiplied fp16-packed x features. Re-zeroes d_deg (last consumer).
__global__ void k_off(const float* __restrict__ x) {
    __shared__ int sm[256];
    __shared__ int base_sh;
    int t = threadIdx.x;
    int n = blockIdx.x * 256 + t;
    int c = (n < N_NODES) ? d_cnt[n] : 0;
    sm[t] = c;
    __syncthreads();
    for (int off = 1; off < 256; off <<= 1) {
        int v = (t >= off) ? sm[t - off] : 0;
        __syncthreads();
        sm[t] += v;
        __syncthreads();
    }
    if (t == 255) base_sh = atomicAdd(&d_total, sm[255]);
    __syncthreads();
    if (n < N_NODES) {
        int o = base_sh + sm[t] - c;   // exclusive within block + block base
        d_off[n] = o;
        int dg = d_deg[n];
        d_deg[n] = 0;                  // restore invariant for next launch
        float dis = (dg > 0) ? rsqrtf((float)dg) : 0.0f;
        d_dis[n] = dis;
        __half2 p01 = __floats2half2_rn(dis * x[n * 3 + 0], dis * x[n * 3 + 1]);
        __half2 p23 = __floats2half2_rn(dis * x[n * 3 + 2], dis);
        uint2 pk;
        pk.x = *(unsigned int*)&p01;
        pk.y = *(unsigned int*)&p23;
        d_xh[n] = pk;
    }
}

// scatter edges grouped by target, 4 edges per thread; ATOMIC-FREE:
// pos = off[col] + rank[e]; one STG.64 per edge.
__global__ void k_scatter(const int* __restrict__ ei, const float* __restrict__ ea) {
    int t = blockIdx.x * blockDim.x + threadIdx.x;
    int e = t * 4;
    if (e >= N_EDGES) return;
    int4 r4 = *(const int4*)&ei[e];
    int4 c4 = *(const int4*)&ei[N_EDGES + e];
    int4 rk = *(const int4*)&d_rank[e];
    float4 ea01 = __ldg(&((const float4*)ea)[t * 2 + 0]);   // ea[e], ea[e+1]
    float4 ea23 = __ldg(&((const float4*)ea)[t * 2 + 1]);   // ea[e+2], ea[e+3]
    __half2 h0 = __floats2half2_rn(ea01.x, ea01.y);
    __half2 h1 = __floats2half2_rn(ea01.z, ea01.w);
    __half2 h2 = __floats2half2_rn(ea23.x, ea23.y);
    __half2 h3 = __floats2half2_rn(ea23.z, ea23.w);
    int p0 = __ldg(&d_off[c4.x]) + rk.x;
    int p1 = __ldg(&d_off[c4.y]) + rk.y;
    int p2 = __ldg(&d_off[c4.z]) + rk.z;
    int p3 = __ldg(&d_off[c4.w]) + rk.w;
    d_csr[p0] = make_int2(r4.x, *(int*)&h0);
    d_csr[p1] = make_int2(r4.y, *(int*)&h1);
    d_csr[p2] = make_int2(r4.z, *(int*)&h2);
    d_csr[p3] = make_int2(r4.w, *(int*)&h3);
}

// layer-1 pull: 8 lanes per node (4 nodes per warp), fp16 premultiplied gathers
// h = relu(x@Wc1+bc1 + (disc*[Σ dis_r*x_r, Σ dis_r*ea]@Wn1)*cinv)
__global__ void k_pull1(const float* __restrict__ x,
                        const float* __restrict__ Wn1,
                        const float* __restrict__ Wc1,
                        const float* __restrict__ bc1) {
    int idx = blockIdx.x * blockDim.x + threadIdx.x;
    int n = idx >> 3;                   // 8 lanes per node
    if (n >= N_NODES) return;
    int sub = threadIdx.x & 7;
    int start = d_off[n];
    int cnt = d_cnt[n];
    int end = start + cnt;
    float a0 = 0.f, a1 = 0.f, a2 = 0.f, a3 = 0.f, a4 = 0.f;
    for (int i = start + sub; i < end; i += 8) {
        int2 en = d_csr[i];
        uint2 xv = __ldg(&d_xh[en.x]);  // {dis*x0, dis*x1 | dis*x2, dis}
        float2 f01 = __half22float2(*(__half2*)&xv.x);
        float2 f23 = __half22float2(*(__half2*)&xv.y);
        float2 eav = __half22float2(*(__half2*)&en.y);
        a0 += f01.x;
        a1 += f01.y;
        a2 += f23.x;
        a3 += f23.y * eav.x;
        a4 += f23.y * eav.y;
    }
#pragma unroll
    for (int o = 4; o; o >>= 1) {       // stays within the 8-lane group
        a0 += __shfl_xor_sync(0xffffffffu, a0, o);
        a1 += __shfl_xor_sync(0xffffffffu, a1, o);
        a2 += __shfl_xor_sync(0xffffffffu, a2, o);
        a3 += __shfl_xor_sync(0xffffffffu, a3, o);
        a4 += __shfl_xor_sync(0xffffffffu, a4, o);
    }
    float disc = d_dis[n];
    float ci = 1.0f / (float)(cnt > 0 ? cnt : 1);
    float dc = disc * ci;
    if (sub == 0) d_zea[n] = make_float2(disc * a3, disc * a4);
    float x0 = __ldg(&x[n * 3 + 0]), x1 = __ldg(&x[n * 3 + 1]), x2 = __ldg(&x[n * 3 + 2]);
#pragma unroll
    for (int q = 0; q < 2; q++) {       // each lane covers columns sub and sub+8
        int j = sub + q * 8;
        float aggr = dc * (a0 * __ldg(&Wn1[0 * F + j]) + a1 * __ldg(&Wn1[1 * F + j]) +
                           a2 * __ldg(&Wn1[2 * F + j]) + a3 * __ldg(&Wn1[3 * F + j]) +
                           a4 * __ldg(&Wn1[4 * F + j]));
        float cent = __ldg(&bc1[j]) + x0 * __ldg(&Wc1[0 * F + j]) +
                     x1 * __ldg(&Wc1[1 * F + j]) + x2 * __ldg(&Wc1[2 * F + j]);
        float v = fmaxf(cent + aggr, 0.0f);
        d_h[n * F + j] = v;
        d_hh[n * F + j] = __float2half(disc * v);   // premultiplied shadow
    }
}

// layer-2 pull: warp per node, feature-parallel lanes.
// lane = (pair p, feature j). Half-warp p walks edges start+p step 2;
// 16 lanes cooperatively read one 32B h-row per edge (1 wavefront).
__global__ void k_pull2(const float* __restrict__ Wn2,
                        const float* __restrict__ Wc2,
                        const float* __restrict__ bc2,
                        const int* __restrict__ batch) {
    int n = (blockIdx.x * blockDim.x + threadIdx.x) >> 5;
    if (n >= N_NODES) return;
    int lane = threadIdx.x & 31;
    int p = lane >> 4;                  // pair 0/1
    int j = lane & 15;                  // feature
    int start = d_off[n];
    int cnt = d_cnt[n];
    int end = start + cnt;
    float acc = 0.0f;
    for (int i = start + p; i < end; i += 2) {
        int r = __ldg(&((const int*)d_csr)[i * 2]);       // .x — broadcast in half-warp
        acc += __half2float(d_hh[r * F + j]);              // 16×2B = one 32B sector
    }
    acc += __shfl_xor_sync(0xffffffffu, acc, 16);          // combine the two pairs
    int g = __ldg(&batch[n]);
    if (lane == 16) d_cnt[n] = 0;       // restore invariant for next launch
    if (lane == 17) atomicAdd(&d_gcnt[g], 1);
    if (lane < F) {
        float disc = d_dis[n];
        float ci = 1.0f / (float)(cnt > 0 ? cnt : 1);
        float2 zea = d_zea[n];
        // gather per-feature sums from the other lanes for the Wn2 GEMV
        float s = 0.0f;
#pragma unroll
        for (int k = 0; k < F; k++) {
            float ak = __shfl_sync(0xffffffffu, acc, k);
            s += ak * __ldg(&Wn2[k * F + j]);
        }
        float aggr = (zea.x * __ldg(&Wn2[16 * F + j]) +
                      zea.y * __ldg(&Wn2[17 * F + j]) + disc * s) * ci;
        float cent = __ldg(&bc2[j]);
        const float* hn = &d_h[n * F];
#pragma unroll
        for (int k = 0; k < F; k++) cent += hn[k] * __ldg(&Wc2[k * F + j]);
        float v = fmaxf(cent + aggr, 0.0f);
        atomicAdd(&d_gsum[g * F + j], v);
    }
}

// head MLP (mean + 2-layer MLP); re-zeroes d_gsum/d_gcnt/d_total
__global__ void k_head(const float* __restrict__ Wl1, const float* __restrict__ bl1,
                       const float* __restrict__ Wl2, const float* __restrict__ bl2,
                       float* __restrict__ out) {
    int g = threadIdx.x;
    if (g >= N_GRAPHS) return;
    if (g == 0) d_total = 0;           // restore invariant for next launch
    int c = d_gcnt[g];
    d_gcnt[g] = 0;
    float inv = 1.0f / (float)(c > 0 ? c : 1);
    float gm[F];
#pragma unroll
    for (int k = 0; k < F; k++) {
        gm[k] = d_gsum[g * F + k] * inv;
        d_gsum[g * F + k] = 0.0f;
    }
    float t[F];
#pragma unroll
    for (int j = 0; j < F; j++) {
        float a = bl1[j];
#pragma unroll
        for (int k = 0; k < F; k++) a += gm[k] * Wl1[k * F + j];
        t[j] = fmaxf(a, 0.0f);
    }
#pragma unroll
    for (int o = 0; o < 2; o++) {
        float a = bl2[o];
#pragma unroll
        for (int j = 0; j < F; j++) a += t[j] * Wl2[j * 2 + o];
        out[g * 2 + o] = a;
    }
}

// ---------------- launch ----------------
extern "C" void kernel_launch(void* const* d_in, const int* in_sizes, int n_in,
                              void* d_out, int out_size) {
    const float* x     = (const float*)d_in[0];
    const int*   ei    = (const int*)d_in[1];
    const float* ea    = (const float*)d_in[2];
    const int*   batch = (const int*)d_in[3];
    const float* Wc1 = (const float*)d_in[4];
    const float* bc1 = (const float*)d_in[5];
    const float* Wn1 = (const float*)d_in[6];
    const float* Wc2 = (const float*)d_in[7];
    const float* bc2 = (const float*)d_in[8];
    const float* Wn2 = (const float*)d_in[9];
    const float* Wl1 = (const float*)d_in[10];
    const float* bl1 = (const float*)d_in[11];
    const float* Wl2 = (const float*)d_in[12];
    const float* bl2 = (const float*)d_in[13];
    float* out = (float*)d_out;

    const int T = 256;
    int eb4 = (N_EDGES / 4 + T - 1) / T;     // 4 edges per thread
    int p1b = (N_NODES * 8 + T - 1) / T;     // 8 lanes per node  (=3125)
    int p2b = (N_NODES * 32 + T - 1) / T;    // warp per node     (=12500)

    k_hist<<<eb4, T>>>(ei);
    k_off<<<NB, T>>>(x);
    k_scatter<<<eb4, T>>>(ei, ea);
    k_pull1<<<p1b, T>>>(x, Wn1, Wc1, bc1);
    k_pull2<<<p2b, T>>>(Wn2, Wc2, bc2, batch);
    k_head<<<1, 64>>>(Wl1, bl1, Wl2, bl2, out);
}

// round 16
// speedup vs baseline: 1.0907x; 1.0907x over previous
#include <cuda_runtime.h>
#include <cuda_bf16.h>
#include <cuda_fp16.h>
#include <math.h>

#define N_NODES 100000
#define N_EDGES 3200000
#define N_GRAPHS 64
#define F 16
#define NB ((N_NODES + 255) / 256)   // 391 blocks of 256

// ---------------- scratch (static device memory; no allocation) ----------------
// Invariant: d_deg, d_cnt, d_gsum, d_gcnt, d_total are ZERO before every launch
// (zero-initialized at load; each launch re-zeroes them after last use).
__device__ int    d_deg[N_NODES];        // out-degree over row (source)
__device__ int    d_cnt[N_NODES];        // in-count over col (target)
__device__ int    d_off[N_NODES];        // CSR offsets
__device__ int    d_rank[N_EDGES];       // edge rank within its target segment (from hist)
__device__ int    d_total;               // running base for block offsets
__device__ int2   d_csr[N_EDGES];        // {row, half2(ea.x, ea.y)}, grouped by col (8B)
__device__ float  d_dis[N_NODES];        // deg_inv_sqrt
__device__ uint2  d_xh[N_NODES];         // {half2(dis*x0, dis*x1), half2(dis*x2, dis)}
__device__ float2 d_zea[N_NODES];        // per-node Σ nr*ea (layer-independent)
__device__ float  d_h[N_NODES * F];      // layer-1 output (fp32, center path)
__device__ __half d_hh[N_NODES * F];     // dis[n]*h[n] fp16 shadow (gather path)
__device__ float  d_gsum[N_GRAPHS * F];  // pooled sums
__device__ int    d_gcnt[N_GRAPHS];      // nodes per graph

// ---------------- kernels ----------------

// histograms, 4 edges per thread; keeps the cnt-atomic return as the edge's rank
__global__ void k_hist(const int* __restrict__ ei) {
    int t = blockIdx.x * blockDim.x + threadIdx.x;
    int e = t * 4;
    if (e >= N_EDGES) return;            // N_EDGES % 4 == 0, no tail
    int4 r4 = *(const int4*)&ei[e];
    int4 c4 = *(const int4*)&ei[N_EDGES + e];
    atomicAdd(&d_deg[r4.x], 1);
    atomicAdd(&d_deg[r4.y], 1);
    atomicAdd(&d_deg[r4.z], 1);
    atomicAdd(&d_deg[r4.w], 1);
    int4 rk;
    rk.x = atomicAdd(&d_cnt[c4.x], 1);
    rk.y = atomicAdd(&d_cnt[c4.y], 1);
    rk.z = atomicAdd(&d_cnt[c4.z], 1);
    rk.w = atomicAdd(&d_cnt[c4.w], 1);
    *(int4*)&d_rank[e] = rk;             // coalesced
}

// offsets via local scan + atomic block base (order-free), fused finalize.
// Stores premultiplied fp16-packed x features. Re-zeroes d_deg (last consumer).
__global__ void k_off(const float* __restrict__ x) {
    __shared__ int sm[256];
    __shared__ int base_sh;
    int t = threadIdx.x;
    int n = blockIdx.x * 256 + t;
    int c = (n < N_NODES) ? d_cnt[n] : 0;
    sm[t] = c;
    __syncthreads();
    for (int off = 1; off < 256; off <<= 1) {
        int v = (t >= off) ? sm[t - off] : 0;
        __syncthreads();
        sm[t] += v;
        __syncthreads();
    }
    if (t == 255) base_sh = atomicAdd(&d_total, sm[255]);
    __syncthreads();
    if (n < N_NODES) {
        int o = base_sh + sm[t] - c;   // exclusive within block + block base
        d_off[n] = o;
        int dg = d_deg[n];
        d_deg[n] = 0;                  // restore invariant for next launch
        float dis = (dg > 0) ? rsqrtf((float)dg) : 0.0f;
        d_dis[n] = dis;
        __half2 p01 = __floats2half2_rn(dis * x[n * 3 + 0], dis * x[n * 3 + 1]);
        __half2 p23 = __floats2half2_rn(dis * x[n * 3 + 2], dis);
        uint2 pk;
        pk.x = *(unsigned int*)&p01;
        pk.y = *(unsigned int*)&p23;
        d_xh[n] = pk;
    }
}

// scatter edges grouped by target, 4 edges per thread; ATOMIC-FREE:
// pos = off[col] + rank[e]; one STG.64 per edge.
__global__ void k_scatter(const int* __restrict__ ei, const float* __restrict__ ea) {
    int t = blockIdx.x * blockDim.x + threadIdx.x;
    int e = t * 4;
    if (e >= N_EDGES) return;
    int4 r4 = *(const int4*)&ei[e];
    int4 c4 = *(const int4*)&ei[N_EDGES + e];
    int4 rk = *(const int4*)&d_rank[e];
    float4 ea01 = __ldg(&((const float4*)ea)[t * 2 + 0]);   // ea[e], ea[e+1]
    float4 ea23 = __ldg(&((const float4*)ea)[t * 2 + 1]);   // ea[e+2], ea[e+3]
    __half2 h0 = __floats2half2_rn(ea01.x, ea01.y);
    __half2 h1 = __floats2half2_rn(ea01.z, ea01.w);
    __half2 h2 = __floats2half2_rn(ea23.x, ea23.y);
    __half2 h3 = __floats2half2_rn(ea23.z, ea23.w);
    int p0 = __ldg(&d_off[c4.x]) + rk.x;
    int p1 = __ldg(&d_off[c4.y]) + rk.y;
    int p2 = __ldg(&d_off[c4.z]) + rk.z;
    int p3 = __ldg(&d_off[c4.w]) + rk.w;
    d_csr[p0] = make_int2(r4.x, *(int*)&h0);
    d_csr[p1] = make_int2(r4.y, *(int*)&h1);
    d_csr[p2] = make_int2(r4.z, *(int*)&h2);
    d_csr[p3] = make_int2(r4.w, *(int*)&h3);
}

// layer-1 pull: 8 lanes per node (4 nodes per warp), fp16 premultiplied gathers
// h = relu(x@Wc1+bc1 + (disc*[Σ dis_r*x_r, Σ dis_r*ea]@Wn1)*cinv)
__global__ void k_pull1(const float* __restrict__ x,
                        const float* __restrict__ Wn1,
                        const float* __restrict__ Wc1,
                        const float* __restrict__ bc1) {
    int idx = blockIdx.x * blockDim.x + threadIdx.x;
    int n = idx >> 3;                   // 8 lanes per node
    if (n >= N_NODES) return;
    int sub = threadIdx.x & 7;
    int start = d_off[n];
    int cnt = d_cnt[n];
    int end = start + cnt;
    float a0 = 0.f, a1 = 0.f, a2 = 0.f, a3 = 0.f, a4 = 0.f;
    for (int i = start + sub; i < end; i += 8) {
        int2 en = d_csr[i];
        uint2 xv = __ldg(&d_xh[en.x]);  // {dis*x0, dis*x1 | dis*x2, dis}
        float2 f01 = __half22float2(*(__half2*)&xv.x);
        float2 f23 = __half22float2(*(__half2*)&xv.y);
        float2 eav = __half22float2(*(__half2*)&en.y);
        a0 += f01.x;
        a1 += f01.y;
        a2 += f23.x;
        a3 += f23.y * eav.x;
        a4 += f23.y * eav.y;
    }
#pragma unroll
    for (int o = 4; o; o >>= 1) {       // stays within the 8-lane group
        a0 += __shfl_xor_sync(0xffffffffu, a0, o);
        a1 += __shfl_xor_sync(0xffffffffu, a1, o);
        a2 += __shfl_xor_sync(0xffffffffu, a2, o);
        a3 += __shfl_xor_sync(0xffffffffu, a3, o);
        a4 += __shfl_xor_sync(0xffffffffu, a4, o);
    }
    float disc = d_dis[n];
    float ci = 1.0f / (float)(cnt > 0 ? cnt : 1);
    float dc = disc * ci;
    if (sub == 0) d_zea[n] = make_float2(disc * a3, disc * a4);
    float x0 = __ldg(&x[n * 3 + 0]), x1 = __ldg(&x[n * 3 + 1]), x2 = __ldg(&x[n * 3 + 2]);
#pragma unroll
    for (int q = 0; q < 2; q++) {       // each lane covers columns sub and sub+8
        int j = sub + q * 8;
        float aggr = dc * (a0 * __ldg(&Wn1[0 * F + j]) + a1 * __ldg(&Wn1[1 * F + j]) +
                           a2 * __ldg(&Wn1[2 * F + j]) + a3 * __ldg(&Wn1[3 * F + j]) +
                           a4 * __ldg(&Wn1[4 * F + j]));
        float cent = __ldg(&bc1[j]) + x0 * __ldg(&Wc1[0 * F + j]) +
                     x1 * __ldg(&Wc1[1 * F + j]) + x2 * __ldg(&Wc1[2 * F + j]);
        float v = fmaxf(cent + aggr, 0.0f);
        d_h[n * F + j] = v;
        d_hh[n * F + j] = __float2half(disc * v);   // premultiplied shadow
    }
}

// layer-2 pull: 16 lanes per node, paired-lane feature-half split.
// Lane = (half h, slot p). Lanes p and p+8 handle the SAME edge in the same
// load instruction -> their two 16B h-row halves coalesce to one 32B wavefront.
__global__ void k_pull2(const float* __restrict__ Wn2,
                        const float* __restrict__ Wc2,
                        const float* __restrict__ bc2,
                        const int* __restrict__ batch) {
    int idx = blockIdx.x * blockDim.x + threadIdx.x;
    int n = idx >> 4;                   // 16 lanes per node
    if (n >= N_NODES) return;
    int sub = threadIdx.x & 15;
    int half = sub >> 3;                // 0: features 0-7, 1: features 8-15
    int slot = sub & 7;                 // edge slot
    int start = d_off[n];
    int cnt = d_cnt[n];
    int end = start + cnt;
    float acc[8];
#pragma unroll
    for (int k = 0; k < 8; k++) acc[k] = 0.0f;
    for (int i = start + slot; i < end; i += 8) {
        int r = __ldg(&((const int*)d_csr)[i * 2]);        // .x (pair lanes broadcast)
        uint4 u = __ldg((const uint4*)&d_hh[r * F + half * 8]);   // 16B; pairs coalesce to 32B
        const __half2* ph = (const __half2*)&u;
#pragma unroll
        for (int w = 0; w < 4; w++) {
            float2 f = __half22float2(ph[w]);
            acc[2 * w + 0] += f.x;
            acc[2 * w + 1] += f.y;
        }
    }
#pragma unroll
    for (int o = 4; o; o >>= 1) {       // butterfly over slots (stays in each half)
#pragma unroll
        for (int k = 0; k < 8; k++) acc[k] += __shfl_xor_sync(0xffffffffu, acc[k], o);
    }
    // now lane (half=0, slot=*) holds feature sums 0-7; (half=1) holds 8-15
    int g = __ldg(&batch[n]);
    if (sub == 1) d_cnt[n] = 0;         // restore invariant for next launch
    if (sub == 2) atomicAdd(&d_gcnt[g], 1);
    {
        int j = sub;
        float disc = d_dis[n];
        float ci = 1.0f / (float)(cnt > 0 ? cnt : 1);
        float2 zea = d_zea[n];
        float s = 0.0f;
#pragma unroll
        for (int k = 0; k < 8; k++) {
            float a_lo = __shfl_sync(0xffffffffu, acc[k], 0, 16);   // features 0-7
            float a_hi = __shfl_sync(0xffffffffu, acc[k], 8, 16);   // features 8-15
            s += a_lo * __ldg(&Wn2[k * F + j]);
            s += a_hi * __ldg(&Wn2[(8 + k) * F + j]);
        }
        float aggr = (zea.x * __ldg(&Wn2[16 * F + j]) +
                      zea.y * __ldg(&Wn2[17 * F + j]) + disc * s) * ci;
        float cent = __ldg(&bc2[j]);
        const float* hn = &d_h[n * F];
#pragma unroll
        for (int k = 0; k < F; k++) cent += hn[k] * __ldg(&Wc2[k * F + j]);
        float v = fmaxf(cent + aggr, 0.0f);
        atomicAdd(&d_gsum[g * F + j], v);
    }
}

// head MLP (mean + 2-layer MLP); re-zeroes d_gsum/d_gcnt/d_total
__global__ void k_head(const float* __restrict__ Wl1, const float* __restrict__ bl1,
                       const float* __restrict__ Wl2, const float* __restrict__ bl2,
                       float* __restrict__ out) {
    int g = threadIdx.x;
    if (g >= N_GRAPHS) return;
    if (g == 0) d_total = 0;           // restore invariant for next launch
    int c = d_gcnt[g];
    d_gcnt[g] = 0;
    float inv = 1.0f / (float)(c > 0 ? c : 1);
    float gm[F];
#pragma unroll
    for (int k = 0; k < F; k++) {
        gm[k] = d_gsum[g * F + k] * inv;
        d_gsum[g * F + k] = 0.0f;
    }
    float t[F];
#pragma unroll
    for (int j = 0; j < F; j++) {
        float a = bl1[j];
#pragma unroll
        for (int k = 0; k < F; k++) a += gm[k] * Wl1[k * F + j];
        t[j] = fmaxf(a, 0.0f);
    }
#pragma unroll
    for (int o = 0; o < 2; o++) {
        float a = bl2[o];
#pragma unroll
        for (int j = 0; j < F; j++) a += t[j] * Wl2[j * 2 + o];
        out[g * 2 + o] = a;
    }
}

// ---------------- launch ----------------
extern "C" void kernel_launch(void* const* d_in, const int* in_sizes, int n_in,
                              void* d_out, int out_size) {
    const float* x     = (const float*)d_in[0];
    const int*   ei    = (const int*)d_in[1];
    const float* ea    = (const float*)d_in[2];
    const int*   batch = (const int*)d_in[3];
    const float* Wc1 = (const float*)d_in[4];
    const float* bc1 = (const float*)d_in[5];
    const float* Wn1 = (const float*)d_in[6];
    const float* Wc2 = (const float*)d_in[7];
    const float* bc2 = (const float*)d_in[8];
    const float* Wn2 = (const float*)d_in[9];
    const float* Wl1 = (const float*)d_in[10];
    const float* bl1 = (const float*)d_in[11];
    const float* Wl2 = (const float*)d_in[12];
    const float* bl2 = (const float*)d_in[13];
    float* out = (float*)d_out;

    const int T = 256;
    int eb4 = (N_EDGES / 4 + T - 1) / T;     // 4 edges per thread
    int p1b = (N_NODES * 8 + T - 1) / T;     // 8 lanes per node  (=3125)
    int p2b = (N_NODES * 16 + T - 1) / T;    // 16 lanes per node (=6250)

    k_hist<<<eb4, T>>>(ei);
    k_off<<<NB, T>>>(x);
    k_scatter<<<eb4, T>>>(ei, ea);
    k_pull1<<<p1b, T>>>(x, Wn1, Wc1, bc1);
    k_pull2<<<p2b, T>>>(Wn2, Wc2, bc2, batch);
    k_head<<<1, 64>>>(Wl1, bl1, Wl2, bl2, out);
}